// round 7
// baseline (speedup 1.0000x reference)
#include <cuda_runtime.h>
#include <math.h>

#define DD 64
#define TWO_PI_F 6.283185307179586f
#define EPS_F 1e-8f

// Device-side scratch (no allocations allowed).
__device__ __align__(16) float g_diag[DD];
__device__ float g_invA[DD * DD];
__device__ float g_coef;
__device__ int g_isdiag;

// ---------------------------------------------------------------------------
// Prep kernel. Diag fast path: vectorized float4 scan of Sigma (off-diag
// check + diagonal gather in one pass), parallel shfl product for det.
// General path: Gauss-Jordan w/ partial pivoting. 1 block, 256 threads.
// ---------------------------------------------------------------------------
__global__ void prep_kernel(const float* __restrict__ Sigma,
                            const float* __restrict__ Phi) {
    __shared__ float aug[DD][2 * DD];
    __shared__ float colk[DD];
    __shared__ float sdiag[DD];
    __shared__ float s_wprod[2];
    __shared__ int s_offdiag;
    __shared__ float s_det;
    __shared__ int s_piv;
    int tid = threadIdx.x;
    int lane = tid & 31;
    int wid = tid >> 5;

    if (tid == 0) s_offdiag = 0;
    __syncthreads();

    // One vectorized pass: 4096 floats = 1024 float4; 256 threads x 4 each,
    // front-batched. Element e=4*v+i: row=e>>6, col=e&63.
    {
        const float4* S4 = reinterpret_cast<const float4*>(Sigma);
        float4 c0 = S4[tid * 4 + 0];
        float4 c1 = S4[tid * 4 + 1];
        float4 c2 = S4[tid * 4 + 2];
        float4 c3 = S4[tid * 4 + 3];
        int bad = 0;
        #pragma unroll
        for (int q = 0; q < 4; q++) {
            float4 c = (q == 0) ? c0 : (q == 1) ? c1 : (q == 2) ? c2 : c3;
            int ebase = (tid * 4 + q) * 4;
            float vals[4] = {c.x, c.y, c.z, c.w};
            #pragma unroll
            for (int i = 0; i < 4; i++) {
                int e = ebase + i;
                int r = e >> 6, col = e & 63;
                if (r == col) sdiag[r] = vals[i];
                else if (vals[i] != 0.0f) bad = 1;
            }
        }
        if (bad) atomicOr(&s_offdiag, 1);
    }
    __syncthreads();

    if (!s_offdiag) {
        if (tid < DD) {
            float v = sdiag[tid];
            g_diag[tid] = (v != 0.0f) ? 1.0f / v : 0.0f;  // pinv semantics
        }
        // Parallel det: warps 0 and 1 each product-reduce 32 diagonal values.
        if (tid < DD) {
            float v = sdiag[tid];
            #pragma unroll
            for (int m = 16; m >= 1; m >>= 1)
                v *= __shfl_xor_sync(0xffffffffu, v, m);
            if (lane == 0) s_wprod[wid] = v;
        }
        __syncthreads();
        if (tid == 0) {
            float det = s_wprod[0] * s_wprod[1];
            g_coef = Phi[0] / sqrtf(TWO_PI_F * det);
            g_isdiag = 1;
        }
        return;
    }

    // --- General path: Gauss-Jordan with partial pivoting on [Sigma | I] ---
    for (int i = tid; i < DD * 2 * DD; i += blockDim.x) {
        int r = i / (2 * DD), c = i % (2 * DD);
        aug[r][c] = (c < DD) ? Sigma[r * DD + c]
                             : ((c - DD == r) ? 1.0f : 0.0f);
    }
    if (tid == 0) s_det = 1.0f;
    __syncthreads();

    for (int k = 0; k < DD; k++) {
        if (tid == 0) {
            int p = k;
            float best = fabsf(aug[k][k]);
            for (int r = k + 1; r < DD; r++) {
                float v = fabsf(aug[r][k]);
                if (v > best) { best = v; p = r; }
            }
            s_piv = p;
            if (p != k) s_det = -s_det;
        }
        __syncthreads();
        int p = s_piv;
        if (p != k) {
            for (int c = tid; c < 2 * DD; c += blockDim.x) {
                float t = aug[k][c];
                aug[k][c] = aug[p][c];
                aug[p][c] = t;
            }
            __syncthreads();
        }
        float piv = aug[k][k];
        if (tid == 0) s_det *= piv;
        float inv_piv = (piv != 0.0f) ? 1.0f / piv : 0.0f;
        for (int c = tid; c < 2 * DD; c += blockDim.x) {
            aug[k][c] *= inv_piv;
        }
        if (tid < DD) colk[tid] = (tid == k) ? 0.0f : aug[tid][k];
        __syncthreads();
        for (int i = tid; i < DD * 2 * DD; i += blockDim.x) {
            int r = i / (2 * DD), c = i % (2 * DD);
            if (r != k) aug[r][c] -= colk[r] * aug[k][c];
        }
        __syncthreads();
    }

    for (int i = tid; i < DD * DD; i += blockDim.x) {
        int r = i >> 6, c = i & 63;
        g_invA[i] = aug[r][DD + c];
    }
    if (tid == 0) {
        g_coef = Phi[0] / sqrtf(TWO_PI_F * s_det);
        g_isdiag = 0;
    }
}

// ---------------------------------------------------------------------------
// Main kernel (diag fast path): persistent grid-stride over 4-sample groups.
// Body identical to the proven R3/R6 config: 4 front-batched __ldcs LDG.128
// per thread (MLP_p1=4), half-warp owns a group, 4 shfl trees, one STG.128.
// grid = 8 CTAs/SM x 148 SMs -> no inter-wave transitions.
// ---------------------------------------------------------------------------
__global__ void __launch_bounds__(256, 8)
density_kernel(const float* __restrict__ x,
               const float* __restrict__ mu,
               float* __restrict__ out, int N, int ngroups) {
    int lane = threadIdx.x & 31;
    int half = lane >> 4;          // 0 or 1
    int sub = lane & 15;           // 16B chunk within sample
    // group index handled by this thread's half-warp
    int g0 = ((blockIdx.x * blockDim.x + threadIdx.x) >> 5) * 2 + half;
    int gstride = (gridDim.x * blockDim.x) >> 4;  // total half-warps

    int isdiag = g_isdiag;
    float coef = g_coef;
    float4 muv = reinterpret_cast<const float4*>(mu)[sub];
    float4 av  = reinterpret_cast<const float4*>(g_diag)[sub];
    const float4* xr = reinterpret_cast<const float4*>(x);

    if (isdiag) {
        for (int g = g0; g < ngroups; g += gstride) {
            int base = g * 4;

            // Front-batched independent streaming loads (read-once data).
            float4 xv0 = __ldcs(&xr[(size_t)(base + 0) * 16 + sub]);
            float4 xv1 = __ldcs(&xr[(size_t)(base + 1) * 16 + sub]);
            float4 xv2 = __ldcs(&xr[(size_t)(base + 2) * 16 + sub]);
            float4 xv3 = __ldcs(&xr[(size_t)(base + 3) * 16 + sub]);

            float p0, p1, p2, p3;
            {
                float d0 = xv0.x - muv.x, d1 = xv0.y - muv.y,
                      d2 = xv0.z - muv.z, d3 = xv0.w - muv.w;
                p0 = av.x * d0 * d0 + av.y * d1 * d1 + av.z * d2 * d2 + av.w * d3 * d3;
            }
            {
                float d0 = xv1.x - muv.x, d1 = xv1.y - muv.y,
                      d2 = xv1.z - muv.z, d3 = xv1.w - muv.w;
                p1 = av.x * d0 * d0 + av.y * d1 * d1 + av.z * d2 * d2 + av.w * d3 * d3;
            }
            {
                float d0 = xv2.x - muv.x, d1 = xv2.y - muv.y,
                      d2 = xv2.z - muv.z, d3 = xv2.w - muv.w;
                p2 = av.x * d0 * d0 + av.y * d1 * d1 + av.z * d2 * d2 + av.w * d3 * d3;
            }
            {
                float d0 = xv3.x - muv.x, d1 = xv3.y - muv.y,
                      d2 = xv3.z - muv.z, d3 = xv3.w - muv.w;
                p3 = av.x * d0 * d0 + av.y * d1 * d1 + av.z * d2 * d2 + av.w * d3 * d3;
            }

            #pragma unroll
            for (int m = 8; m >= 1; m >>= 1) {
                p0 += __shfl_xor_sync(0xffffffffu, p0, m);
                p1 += __shfl_xor_sync(0xffffffffu, p1, m);
                p2 += __shfl_xor_sync(0xffffffffu, p2, m);
                p3 += __shfl_xor_sync(0xffffffffu, p3, m);
            }

            if (sub == 0) {
                float4 r;
                r.x = -__logf(coef * __expf(-0.5f * p0) + EPS_F);
                r.y = -__logf(coef * __expf(-0.5f * p1) + EPS_F);
                r.z = -__logf(coef * __expf(-0.5f * p2) + EPS_F);
                r.w = -__logf(coef * __expf(-0.5f * p3) + EPS_F);
                *reinterpret_cast<float4*>(out + base) = r;
            }
        }
    } else {
        // General quadratic form (cold path).
        if (sub == 0) {
            for (int g = g0; g < ngroups; g += gstride) {
                int base = g * 4;
                for (int j = 0; j < 4; j++) {
                    int s = base + j;
                    if (s >= N) break;
                    const float* xrow = x + (size_t)s * DD;
                    float q = 0.0f;
#pragma unroll 1
                    for (int e = 0; e < DD; e++) {
                        float de = xrow[e] - mu[e];
                        float t = 0.0f;
#pragma unroll 8
                        for (int d = 0; d < DD; d++)
                            t += g_invA[e * DD + d] * (xrow[d] - mu[d]);
                        q += de * t;
                    }
                    float dens = g_coef * __expf(-0.5f * q);
                    out[s] = -__logf(dens + EPS_F);
                }
            }
        }
    }
}

extern "C" void kernel_launch(void* const* d_in, const int* in_sizes, int n_in,
                              void* d_out, int out_size) {
    const float* samples = (const float*)d_in[0];
    const float* Phi     = (const float*)d_in[1];
    const float* mu      = (const float*)d_in[2];
    const float* Sigma   = (const float*)d_in[3];
    int N = out_size;  // one output per sample (N = 1048576, divisible by 4)

    prep_kernel<<<1, 256>>>(Sigma, Phi);

    int ngroups = N / 4;                 // 4-sample groups
    int blocks = 148 * 8;                // persistent: one full wave
    density_kernel<<<blocks, 256>>>(samples, mu, (float*)d_out, N, ngroups);
}